// round 5
// baseline (speedup 1.0000x reference)
#include <cuda_runtime.h>
#include <cuda_bf16.h>

// ChamferLoss, single-launch fused version (R5).
// Compute identical to R4 (balanced 148-CTA persistent kernel, packed f32x2
// FMA chain on 0.5*d^2, sqrt hoisted outside the mins). New: the column-sum
// and final reduction are fused into the same kernel.
//  - Per pair, the LAST CTA to flush its column mins (per-pair ticket; flusher
//    count known in closed form from the contiguous tile split) immediately
//    computes that pair's column distance sum, reading g_colmin with __ldcg
//    (L1 bypass -> sees all L2 atomicMax results) and resetting slots to 0 for
//    the next graph replay. This overlaps with other CTAs' compute.
//  - A global done-ticket makes the last CTA overall do the fixed-order final
//    reduction. One kernel launch total.
// Determinism: mins are exact; every sum is fixed-order; values independent of
// which CTA executes the shared epilogues.

#define NPTS    1024
#define THREADS 256
#define NWARPS  8
#define CBMAX   128
#define NCTA    148

typedef unsigned long long ull;

#define PACK2(d, lo, hi) \
    asm("mov.b64 %0, {%1,%2};" : "=l"(d) : "f"(lo), "f"(hi))
#define UNPACK2(lo, hi, s) \
    asm("mov.b64 {%0,%1}, %2;" : "=f"(lo), "=f"(hi) : "l"(s))
#define FMA2(d, a, b, c) \
    asm("fma.rn.f32x2 %0, %1, %2, %3;" : "=l"(d) : "l"(a), "l"(b), "l"(c))
#define ADD2(d, a, b) \
    asm("add.rn.f32x2 %0, %1, %2;" : "=l"(d) : "l"(a), "l"(b))

__device__ unsigned g_colmin[CBMAX * NPTS];  // zero-init; key = ~bits(min 0.5*d2)
__device__ float    g_rowpart[NCTA];
__device__ float    g_pairsum[CBMAX];
__device__ int      g_paircnt[CBMAX];        // zero-init; reset by consumer
__device__ int      g_done;                  // zero-init; reset by last CTA

__global__ __launch_bounds__(THREADS, 1)
void chamfer_fused(const float* __restrict__ p, const float* __restrict__ q,
                   float* __restrict__ out, int ntiles, int ncta, int npairs) {
    __shared__ __align__(16) float qx_s[NPTS], qy_s[NPTS], qz_s[NPTS], qs_s[NPTS];
    __shared__ __align__(16) float px_s[NPTS], py_s[NPTS], pz_s[NPTS], ps_s[NPTS];
    __shared__ float sred[NWARPS];
    __shared__ int amlast;

    const int cta  = blockIdx.x;
    const int tid  = threadIdx.x;
    const int warp = tid >> 5;
    const int lane = tid & 31;
    const float INF = __int_as_float(0x7f800000);

    const int t0 = (cta * ntiles) / ncta;
    const int t1 = ((cta + 1) * ntiles) / ncta;

    float rowsum = 0.0f;

    int t = t0;
    while (t < t1) {
        const int pair = t >> 3;

        // ---- stage pair data (SoA, p negated, half-norms) ----
        __syncthreads();  // protect smem reuse from previous pair's merge
        {
            const float4* __restrict__ qp =
                reinterpret_cast<const float4*>(q) + (size_t)pair * NPTS;
            const float4* __restrict__ pp =
                reinterpret_cast<const float4*>(p) + (size_t)pair * NPTS;
            for (int i = tid; i < NPTS; i += THREADS) {
                float4 v = qp[i];
                qx_s[i] = v.y; qy_s[i] = v.z; qz_s[i] = v.w;
                qs_s[i] = 0.5f * (v.y * v.y + v.z * v.z + v.w * v.w);
                float4 u = pp[i];
                px_s[i] = -u.y; py_s[i] = -u.z; pz_s[i] = -u.w;
                ps_s[i] = 0.5f * (u.y * u.y + u.z * u.z + u.w * u.w);
            }
        }
        __syncthreads();

        float colmin[32];
        #pragma unroll
        for (int j = 0; j < 32; ++j) colmin[j] = INF;

        // ---- all tiles of this pair within [t0,t1) ----
        do {
            const int rb = t & 7;
            #pragma unroll
            for (int g = 0; g < 2; ++g) {
                const int row0 = rb * 128 + warp * 16 + g * 8;
                ull pnx2[8], pny2[8], pnz2[8], psq2[8];
                float rmin[8];
                #pragma unroll
                for (int r = 0; r < 8; ++r) {
                    int row = row0 + r;
                    float a = px_s[row], b = py_s[row];   // broadcast LDS
                    float c = pz_s[row], s = ps_s[row];
                    PACK2(pnx2[r], a, a);
                    PACK2(pny2[r], b, b);
                    PACK2(pnz2[r], c, c);
                    PACK2(psq2[r], s, s);
                    rmin[r] = INF;
                }
                #pragma unroll
                for (int j2 = 0; j2 < 16; ++j2) {
                    const int base = (j2 << 6) + (lane << 1);  // 8B-aligned
                    ull xx2 = *reinterpret_cast<const ull*>(qx_s + base);
                    ull yy2 = *reinterpret_cast<const ull*>(qy_s + base);
                    ull zz2 = *reinterpret_cast<const ull*>(qz_s + base);
                    ull ss2 = *reinterpret_cast<const ull*>(qs_s + base);
                    #pragma unroll
                    for (int r = 0; r < 8; ++r) {
                        ull acc;
                        ADD2(acc, ss2, psq2[r]);        // 0.5|q|^2+0.5|p|^2 (2 cols)
                        FMA2(acc, pnx2[r], xx2, acc);   // - px*qx
                        FMA2(acc, pny2[r], yy2, acc);
                        FMA2(acc, pnz2[r], zz2, acc);   // acc = 0.5*d2 (2 cols)
                        float u0, u1;
                        UNPACK2(u0, u1, acc);
                        colmin[2 * j2]     = fminf(colmin[2 * j2],     u0);
                        colmin[2 * j2 + 1] = fminf(colmin[2 * j2 + 1], u1);
                        rmin[r] = fminf(rmin[r], fminf(u0, u1));
                    }
                }
                #pragma unroll
                for (int r = 0; r < 8; ++r) {
                    float m = rmin[r];
                    #pragma unroll
                    for (int off = 16; off > 0; off >>= 1)
                        m = fminf(m, __shfl_xor_sync(0xffffffffu, m, off));
                    rowsum += sqrtf(fmaxf(2.0f * m, 0.0f) + 1e-12f);  // lane-uniform
                }
            }
            ++t;
        } while (t < t1 && (t >> 3) == pair);

        // ---- flush this pair's column mins (single lexical site) ----
        {
            float* mrgf = px_s;  // reuse px..ps block (16KB) as merge scratch
            #pragma unroll
            for (int half = 0; half < 2; ++half) {
                __syncthreads();
                #pragma unroll
                for (int j2h = 0; j2h < 8; ++j2h) {
                    const int j2 = half * 8 + j2h;
                    ull pk;
                    PACK2(pk, colmin[2 * j2], colmin[2 * j2 + 1]);
                    *reinterpret_cast<ull*>(mrgf + warp * 512 + (j2h << 6) + (lane << 1)) = pk;
                }
                __syncthreads();
                for (int c0 = tid; c0 < 512; c0 += THREADS) {
                    float m = mrgf[c0];
                    #pragma unroll
                    for (int w = 1; w < NWARPS; ++w)
                        m = fminf(m, mrgf[w * 512 + c0]);
                    unsigned key = ~__float_as_uint(fmaxf(m, 0.0f));
                    atomicMax(&g_colmin[pair * NPTS + half * 512 + c0], key);
                }
            }
        }

        // ---- pair ticket: last flusher computes this pair's column sum ----
        __threadfence();
        __syncthreads();
        if (tid == 0) {
            // flusher count for this pair from the contiguous split:
            // cta owning tile t is ((t+1)*ncta - 1) / ntiles
            int clo = ((pair * 8 + 1) * ncta - 1) / ntiles;
            int chi = ((pair * 8 + 8) * ncta - 1) / ntiles;
            int nflush = chi - clo + 1;
            int prev = atomicAdd(&g_paircnt[pair], 1);
            amlast = (prev == nflush - 1) ? 1 : 0;
        }
        __syncthreads();
        if (amlast) {
            // All flushers' atomicMax are in L2; __ldcg bypasses L1.
            const uint4* src = reinterpret_cast<const uint4*>(g_colmin) + pair * (NPTS / 4) + tid;
            uint4 k = __ldcg(src);
            // reset for next graph replay (plain store reaches L2 before kernel end)
            uint4* dst = reinterpret_cast<uint4*>(g_colmin) + pair * (NPTS / 4) + tid;
            *dst = make_uint4(0u, 0u, 0u, 0u);
            float s = sqrtf(2.0f * __uint_as_float(~k.x) + 1e-12f)
                    + sqrtf(2.0f * __uint_as_float(~k.y) + 1e-12f)
                    + sqrtf(2.0f * __uint_as_float(~k.z) + 1e-12f)
                    + sqrtf(2.0f * __uint_as_float(~k.w) + 1e-12f);
            #pragma unroll
            for (int off = 16; off > 0; off >>= 1)
                s += __shfl_xor_sync(0xffffffffu, s, off);
            if (lane == 0) sred[warp] = s;
            __syncthreads();
            if (tid == 0) {
                float b = 0.0f;
                #pragma unroll
                for (int w = 0; w < NWARPS; ++w) b += sred[w];
                g_pairsum[pair] = b;
                g_paircnt[pair] = 0;  // reset ticket for next replay
            }
            __syncthreads();  // sred reuse safety
        }
    }

    // ---- row-distance partial for this CTA ----
    __syncthreads();
    if (lane == 0) sred[warp] = rowsum;  // rowsum lane-uniform
    __syncthreads();
    if (tid == 0) {
        float s = 0.0f;
        #pragma unroll
        for (int w = 0; w < NWARPS; ++w) s += sred[w];
        g_rowpart[cta] = s;
        __threadfence();
        int prev = atomicAdd(&g_done, 1);
        amlast = (prev == ncta - 1) ? 1 : 0;
    }
    __syncthreads();

    // ---- globally last CTA: deterministic fixed-order final reduction ----
    if (amlast) {
        __threadfence();
        float v = 0.0f;
        if (tid < npairs) v += __ldcg(&g_pairsum[tid]);
        if (tid < ncta)   v += __ldcg(&g_rowpart[tid]);
        #pragma unroll
        for (int off = 16; off > 0; off >>= 1)
            v += __shfl_xor_sync(0xffffffffu, v, off);
        if ((tid & 31) == 0) sred[tid >> 5] = v;
        __syncthreads();
        if (tid == 0) {
            float tot = 0.0f;
            #pragma unroll
            for (int w = 0; w < NWARPS; ++w) tot += sred[w];
            out[0] = tot;
            g_done = 0;  // reset for next replay
        }
    }
}

extern "C" void kernel_launch(void* const* d_in, const int* in_sizes, int n_in,
                              void* d_out, int out_size) {
    const float* p = (const float*)d_in[0];
    const float* q = (const float*)d_in[1];
    float* out = (float*)d_out;

    int cb = in_sizes[0] / (NPTS * 4);  // 128 for (2,64,1024,4)
    if (cb > CBMAX) cb = CBMAX;
    int ntiles = cb * 8;
    int ncta = NCTA;
    if (ncta > ntiles) ncta = ntiles;

    chamfer_fused<<<ncta, THREADS>>>(p, q, out, ntiles, ncta, cb);
}

// round 6
// speedup vs baseline: 1.0281x; 1.0281x over previous
#include <cuda_runtime.h>
#include <cuda_bf16.h>

// ChamferLoss R6: single launch, epilogue moved to kernel TAIL (R5's in-loop
// fusion blew regs to 254 and stalled the fma pipe at 29%).
// Main loop == proven R4: 148 balanced CTAs, <=7 tiles (pair,128-row block)
// each; q & p staged in SMEM (SoA, p negated, half-norms); u = 0.5*d^2 via
// packed f32x2 FMA; sqrt hoisted past the mins. Column mins merged via SMEM
// tree + one atomicMax per column on COMPLEMENTED float bits (zero-identity,
// consumer resets -> graph-replay safe).
// In-loop per-pair ticket only RECORDS ownership (last flusher, closed-form
// flusher count). Tail: owner CTAs (<=2 pairs each) do the pair colsums with
// __ldcg; global done-ticket; last CTA does the fixed-order final reduction.
// Fully deterministic.

#define NPTS    1024
#define THREADS 256
#define NWARPS  8
#define CBMAX   128
#define NCTA    148

typedef unsigned long long ull;

#define PACK2(d, lo, hi) \
    asm("mov.b64 %0, {%1,%2};" : "=l"(d) : "f"(lo), "f"(hi))
#define UNPACK2(lo, hi, s) \
    asm("mov.b64 {%0,%1}, %2;" : "=f"(lo), "=f"(hi) : "l"(s))
#define FMA2(d, a, b, c) \
    asm("fma.rn.f32x2 %0, %1, %2, %3;" : "=l"(d) : "l"(a), "l"(b), "l"(c))
#define ADD2(d, a, b) \
    asm("add.rn.f32x2 %0, %1, %2;" : "=l"(d) : "l"(a), "l"(b))

__device__ unsigned g_colmin[CBMAX * NPTS];  // zero-init; key = ~bits(min 0.5*d2)
__device__ float    g_rowpart[NCTA];
__device__ float    g_pairsum[CBMAX];
__device__ int      g_paircnt[CBMAX];        // zero-init; reset by owner
__device__ int      g_done;                  // zero-init; reset by last CTA

__global__ __launch_bounds__(THREADS, 1)
void chamfer_fused(const float* __restrict__ p, const float* __restrict__ q,
                   float* __restrict__ out, int ntiles, int ncta, int npairs) {
    __shared__ __align__(16) float qx_s[NPTS], qy_s[NPTS], qz_s[NPTS], qs_s[NPTS];
    __shared__ __align__(16) float px_s[NPTS], py_s[NPTS], pz_s[NPTS], ps_s[NPTS];
    __shared__ float sred[NWARPS];
    __shared__ int sh_flag;

    const int cta  = blockIdx.x;
    const int tid  = threadIdx.x;
    const int warp = tid >> 5;
    const int lane = tid & 31;
    const float INF = __int_as_float(0x7f800000);

    const int t0 = (cta * ntiles) / ncta;
    const int t1 = ((cta + 1) * ntiles) / ncta;

    float rowsum = 0.0f;
    int own0 = -1, own1 = -1;   // pairs this CTA must column-sum in the tail

    int t = t0;
    while (t < t1) {
        const int pair = t >> 3;

        // ---- stage pair data (SoA, p negated, half-norms) ----
        __syncthreads();  // protect smem reuse from previous pair's merge
        {
            const float4* __restrict__ qp =
                reinterpret_cast<const float4*>(q) + (size_t)pair * NPTS;
            const float4* __restrict__ pp =
                reinterpret_cast<const float4*>(p) + (size_t)pair * NPTS;
            for (int i = tid; i < NPTS; i += THREADS) {
                float4 v = qp[i];
                qx_s[i] = v.y; qy_s[i] = v.z; qz_s[i] = v.w;
                qs_s[i] = 0.5f * (v.y * v.y + v.z * v.z + v.w * v.w);
                float4 u = pp[i];
                px_s[i] = -u.y; py_s[i] = -u.z; pz_s[i] = -u.w;
                ps_s[i] = 0.5f * (u.y * u.y + u.z * u.z + u.w * u.w);
            }
        }
        __syncthreads();

        float colmin[32];
        #pragma unroll
        for (int j = 0; j < 32; ++j) colmin[j] = INF;

        // ---- all tiles of this pair within [t0,t1) ----
        do {
            const int rb = t & 7;
            #pragma unroll
            for (int g = 0; g < 2; ++g) {
                const int row0 = rb * 128 + warp * 16 + g * 8;
                ull pnx2[8], pny2[8], pnz2[8], psq2[8];
                float rmin[8];
                #pragma unroll
                for (int r = 0; r < 8; ++r) {
                    int row = row0 + r;
                    float a = px_s[row], b = py_s[row];   // broadcast LDS
                    float c = pz_s[row], s = ps_s[row];
                    PACK2(pnx2[r], a, a);
                    PACK2(pny2[r], b, b);
                    PACK2(pnz2[r], c, c);
                    PACK2(psq2[r], s, s);
                    rmin[r] = INF;
                }
                #pragma unroll
                for (int j2 = 0; j2 < 16; ++j2) {
                    const int base = (j2 << 6) + (lane << 1);  // 8B-aligned
                    ull xx2 = *reinterpret_cast<const ull*>(qx_s + base);
                    ull yy2 = *reinterpret_cast<const ull*>(qy_s + base);
                    ull zz2 = *reinterpret_cast<const ull*>(qz_s + base);
                    ull ss2 = *reinterpret_cast<const ull*>(qs_s + base);
                    #pragma unroll
                    for (int r = 0; r < 8; ++r) {
                        ull acc;
                        ADD2(acc, ss2, psq2[r]);        // 0.5|q|^2+0.5|p|^2 (2 cols)
                        FMA2(acc, pnx2[r], xx2, acc);   // - px*qx
                        FMA2(acc, pny2[r], yy2, acc);
                        FMA2(acc, pnz2[r], zz2, acc);   // acc = 0.5*d2 (2 cols)
                        float u0, u1;
                        UNPACK2(u0, u1, acc);
                        colmin[2 * j2]     = fminf(colmin[2 * j2],     u0);
                        colmin[2 * j2 + 1] = fminf(colmin[2 * j2 + 1], u1);
                        rmin[r] = fminf(rmin[r], fminf(u0, u1));
                    }
                }
                #pragma unroll
                for (int r = 0; r < 8; ++r) {
                    float m = rmin[r];
                    #pragma unroll
                    for (int off = 16; off > 0; off >>= 1)
                        m = fminf(m, __shfl_xor_sync(0xffffffffu, m, off));
                    rowsum += sqrtf(fmaxf(2.0f * m, 0.0f) + 1e-12f);  // lane-uniform
                }
            }
            ++t;
        } while (t < t1 && (t >> 3) == pair);

        // ---- flush this pair's column mins ----
        {
            float* mrgf = px_s;  // reuse px..ps block (16KB) as merge scratch
            #pragma unroll
            for (int half = 0; half < 2; ++half) {
                __syncthreads();
                #pragma unroll
                for (int j2h = 0; j2h < 8; ++j2h) {
                    const int j2 = half * 8 + j2h;
                    ull pk;
                    PACK2(pk, colmin[2 * j2], colmin[2 * j2 + 1]);
                    *reinterpret_cast<ull*>(mrgf + warp * 512 + (j2h << 6) + (lane << 1)) = pk;
                }
                __syncthreads();
                for (int c0 = tid; c0 < 512; c0 += THREADS) {
                    float m = mrgf[c0];
                    #pragma unroll
                    for (int w = 1; w < NWARPS; ++w)
                        m = fminf(m, mrgf[w * 512 + c0]);
                    unsigned key = ~__float_as_uint(fmaxf(m, 0.0f));
                    atomicMax(&g_colmin[pair * NPTS + half * 512 + c0], key);
                }
            }
        }

        // ---- per-pair ticket: RECORD ownership only (no epilogue work here) ----
        __syncthreads();
        if (tid == 0) {
            // cta owning tile t is ((t+1)*ncta - 1) / ntiles
            __threadfence();  // order our atomicMax before the ticket (cumulative w/ sync)
            int clo = ((pair * 8 + 1) * ncta - 1) / ntiles;
            int chi = ((pair * 8 + 8) * ncta - 1) / ntiles;
            int nflush = chi - clo + 1;
            int prev = atomicAdd(&g_paircnt[pair], 1);
            sh_flag = (prev == nflush - 1) ? 1 : 0;
        }
        __syncthreads();
        if (sh_flag) { own1 = own0; own0 = pair; }
    }

    // ======================= TAIL =======================

    // row-distance partial for this CTA
    __syncthreads();
    if (lane == 0) sred[warp] = rowsum;  // rowsum lane-uniform
    __syncthreads();
    if (tid == 0) {
        float s = 0.0f;
        #pragma unroll
        for (int w = 0; w < NWARPS; ++w) s += sred[w];
        g_rowpart[cta] = s;
    }

    // column sums for owned pairs (all flushes for them are complete)
    __threadfence();  // acquire side: observe other CTAs' atomicMax results
    #pragma unroll
    for (int o = 0; o < 2; ++o) {
        int pr = (o == 0) ? own0 : own1;
        if (pr >= 0) {
            __syncthreads();
            const uint4* src = reinterpret_cast<const uint4*>(g_colmin) + pr * (NPTS / 4) + tid;
            uint4 k = __ldcg(src);  // bypass L1 -> see all L2 atomic results
            uint4* dst = reinterpret_cast<uint4*>(g_colmin) + pr * (NPTS / 4) + tid;
            *dst = make_uint4(0u, 0u, 0u, 0u);   // reset for next graph replay
            float s = sqrtf(2.0f * __uint_as_float(~k.x) + 1e-12f)
                    + sqrtf(2.0f * __uint_as_float(~k.y) + 1e-12f)
                    + sqrtf(2.0f * __uint_as_float(~k.z) + 1e-12f)
                    + sqrtf(2.0f * __uint_as_float(~k.w) + 1e-12f);
            #pragma unroll
            for (int off = 16; off > 0; off >>= 1)
                s += __shfl_xor_sync(0xffffffffu, s, off);
            if (lane == 0) sred[warp] = s;
            __syncthreads();
            if (tid == 0) {
                float b = 0.0f;
                #pragma unroll
                for (int w = 0; w < NWARPS; ++w) b += sred[w];
                g_pairsum[pr] = b;
                g_paircnt[pr] = 0;  // reset ticket for next replay
            }
        }
    }

    // global done-ticket; last CTA does the deterministic final reduction
    __syncthreads();
    if (tid == 0) {
        __threadfence();  // order rowpart + pairsum stores before the ticket
        int prev = atomicAdd(&g_done, 1);
        sh_flag = (prev == ncta - 1) ? 1 : 0;
    }
    __syncthreads();
    if (sh_flag) {
        __threadfence();
        float v = 0.0f;
        if (tid < npairs) v += __ldcg(&g_pairsum[tid]);
        if (tid < ncta)   v += __ldcg(&g_rowpart[tid]);
        #pragma unroll
        for (int off = 16; off > 0; off >>= 1)
            v += __shfl_xor_sync(0xffffffffu, v, off);
        if ((tid & 31) == 0) sred[tid >> 5] = v;
        __syncthreads();
        if (tid == 0) {
            float tot = 0.0f;
            #pragma unroll
            for (int w = 0; w < NWARPS; ++w) tot += sred[w];
            out[0] = tot;
            g_done = 0;  // reset for next replay
        }
    }
}

extern "C" void kernel_launch(void* const* d_in, const int* in_sizes, int n_in,
                              void* d_out, int out_size) {
    const float* p = (const float*)d_in[0];
    const float* q = (const float*)d_in[1];
    float* out = (float*)d_out;

    int cb = in_sizes[0] / (NPTS * 4);  // 128 for (2,64,1024,4)
    if (cb > CBMAX) cb = CBMAX;
    int ntiles = cb * 8;
    int ncta = NCTA;
    if (ncta > ntiles) ncta = ntiles;

    chamfer_fused<<<ncta, THREADS>>>(p, q, out, ntiles, ncta, cb);
}

// round 7
// speedup vs baseline: 1.0838x; 1.0542x over previous
#include <cuda_runtime.h>
#include <cuda_bf16.h>

// ChamferLoss R7 = proven R2 kernel (40.7us main) with the final reduction
// fused into the kernel tail via a done-ticket (removes the 4.5us second
// launch). Hot loop untouched: one CTA per (c,b) pair; p,q staged in SMEM
// (SoA, p pre-negated, half-norms precomputed); u = 0.5*d^2 via packed f32x2
// FMA chain; sqrt hoisted outside the mins; column mins merged per-CTA with
// SMEM atomicMin on clamped uint bits. Fully deterministic.

#define NPTS    1024
#define THREADS 256
#define NWARPS  8
#define ROWS_PER_WARP 128
#define RG      8
#define CB_MAX  128

typedef unsigned long long ull;

#define PACK2(d, lo, hi) \
    asm("mov.b64 %0, {%1,%2};" : "=l"(d) : "f"(lo), "f"(hi))
#define UNPACK2(lo, hi, s) \
    asm("mov.b64 {%0,%1}, %2;" : "=f"(lo), "=f"(hi) : "l"(s))
#define FMA2(d, a, b, c) \
    asm("fma.rn.f32x2 %0, %1, %2, %3;" : "=l"(d) : "l"(a), "l"(b), "l"(c))
#define ADD2(d, a, b) \
    asm("add.rn.f32x2 %0, %1, %2;" : "=l"(d) : "l"(a), "l"(b))

__device__ float g_partials[CB_MAX];
__device__ int   g_done;   // zero-init; reset by last CTA each run

__global__ __launch_bounds__(THREADS, 1)
void chamfer_pair_kernel(const float* __restrict__ p, const float* __restrict__ q,
                         float* __restrict__ out, int cb_count) {
    __shared__ __align__(16) float qx_s[NPTS], qy_s[NPTS], qz_s[NPTS], qs_s[NPTS];
    __shared__ __align__(16) float px_s[NPTS], py_s[NPTS], pz_s[NPTS], ps_s[NPTS];
    __shared__ unsigned colmin_sh[NPTS];
    __shared__ float warp_rowsum[NWARPS];
    __shared__ float warp_colsum[NWARPS];
    __shared__ int sh_last;

    const int cb  = blockIdx.x;
    const int tid = threadIdx.x;
    const float4* __restrict__ qp = reinterpret_cast<const float4*>(q) + (size_t)cb * NPTS;
    const float4* __restrict__ pp = reinterpret_cast<const float4*>(p) + (size_t)cb * NPTS;

    // Stage both point sets (SoA). p pre-negated; half squared norms precomputed.
    for (int i = tid; i < NPTS; i += THREADS) {
        float4 v = qp[i];
        qx_s[i] = v.y; qy_s[i] = v.z; qz_s[i] = v.w;
        qs_s[i] = 0.5f * (v.y * v.y + v.z * v.z + v.w * v.w);
        float4 u = pp[i];
        px_s[i] = -u.y; py_s[i] = -u.z; pz_s[i] = -u.w;
        ps_s[i] = 0.5f * (u.y * u.y + u.z * u.z + u.w * u.w);
        colmin_sh[i] = 0x7f800000u;  // +inf bits
    }
    __syncthreads();

    const int warp = tid >> 5;
    const int lane = tid & 31;
    const float INF = __int_as_float(0x7f800000);

    // Lane owns columns (j2*64 + lane*2 + {0,1}), j2 = 0..15.
    float colmin[32];
    #pragma unroll
    for (int j = 0; j < 32; ++j) colmin[j] = INF;

    float rowsum = 0.0f;
    const int row0 = warp * ROWS_PER_WARP;

    for (int rg = 0; rg < ROWS_PER_WARP; rg += RG) {
        ull pnx2[RG], pny2[RG], pnz2[RG], psq2[RG];
        float rmin[RG];
        #pragma unroll
        for (int r = 0; r < RG; ++r) {
            int row = row0 + rg + r;
            float a = px_s[row], b = py_s[row], c = pz_s[row], d = ps_s[row];
            PACK2(pnx2[r], a, a);
            PACK2(pny2[r], b, b);
            PACK2(pnz2[r], c, c);
            PACK2(psq2[r], d, d);
            rmin[r] = INF;
        }
        #pragma unroll
        for (int j2 = 0; j2 < 16; ++j2) {
            const int base = (j2 << 6) + (lane << 1);   // 8B-aligned
            ull xx2 = *reinterpret_cast<const ull*>(qx_s + base);
            ull yy2 = *reinterpret_cast<const ull*>(qy_s + base);
            ull zz2 = *reinterpret_cast<const ull*>(qz_s + base);
            ull ss2 = *reinterpret_cast<const ull*>(qs_s + base);
            #pragma unroll
            for (int r = 0; r < RG; ++r) {
                ull acc;
                ADD2(acc, ss2, psq2[r]);          // 0.5|q|^2 + 0.5|p|^2 (2 cols)
                FMA2(acc, pnx2[r], xx2, acc);     // - px*qx
                FMA2(acc, pny2[r], yy2, acc);
                FMA2(acc, pnz2[r], zz2, acc);     // acc = 0.5*d2 for 2 columns
                float u0, u1;
                UNPACK2(u0, u1, acc);
                colmin[2 * j2]     = fminf(colmin[2 * j2],     u0);
                colmin[2 * j2 + 1] = fminf(colmin[2 * j2 + 1], u1);
                rmin[r] = fminf(rmin[r], fminf(u0, u1));
            }
        }
        // Row mins across lanes; one sqrt per row.
        #pragma unroll
        for (int r = 0; r < RG; ++r) {
            float m = rmin[r];
            #pragma unroll
            for (int off = 16; off > 0; off >>= 1)
                m = fminf(m, __shfl_xor_sync(0xffffffffu, m, off));
            rowsum += sqrtf(fmaxf(2.0f * m, 0.0f) + 1e-12f);  // same on all lanes
        }
    }

    // Merge per-warp column mins (clamped >= 0 -> uint order == float order).
    #pragma unroll
    for (int j2 = 0; j2 < 16; ++j2) {
        #pragma unroll
        for (int k = 0; k < 2; ++k) {
            int c = (j2 << 6) + (lane << 1) + k;
            float v = fmaxf(colmin[2 * j2 + k], 0.0f);
            atomicMin(&colmin_sh[c], __float_as_uint(v));
        }
    }
    if (lane == 0) warp_rowsum[warp] = rowsum;
    __syncthreads();

    // Column distance sums.
    float csum = 0.0f;
    for (int i = tid; i < NPTS; i += THREADS) {
        float v = __uint_as_float(colmin_sh[i]);  // already clamped >= 0
        csum += sqrtf(2.0f * v + 1e-12f);
    }
    #pragma unroll
    for (int off = 16; off > 0; off >>= 1)
        csum += __shfl_xor_sync(0xffffffffu, csum, off);
    if (lane == 0) warp_colsum[warp] = csum;
    __syncthreads();

    // Per-CTA total + done-ticket.
    if (tid == 0) {
        float total = 0.0f;
        #pragma unroll
        for (int w = 0; w < NWARPS; ++w) total += warp_rowsum[w] + warp_colsum[w];
        g_partials[cb] = total;
        __threadfence();                       // partial visible before ticket
        int prev = atomicAdd(&g_done, 1);
        sh_last = (prev == cb_count - 1) ? 1 : 0;
    }
    __syncthreads();

    // Last CTA: deterministic fixed-order final reduction over all pairs.
    if (sh_last) {
        __threadfence();                       // observe all partials (L2)
        float v = (tid < cb_count) ? __ldcg(&g_partials[tid]) : 0.0f;
        #pragma unroll
        for (int off = 16; off > 0; off >>= 1)
            v += __shfl_xor_sync(0xffffffffu, v, off);
        if (lane == 0) warp_rowsum[warp] = v;  // reuse as scratch (safe: all
        __syncthreads();                       //  CTAs past prior reads)
        if (tid == 0) {
            float tot = 0.0f;
            #pragma unroll
            for (int w = 0; w < NWARPS; ++w) tot += warp_rowsum[w];
            out[0] = tot;
            g_done = 0;                        // reset for next graph replay
        }
    }
}

extern "C" void kernel_launch(void* const* d_in, const int* in_sizes, int n_in,
                              void* d_out, int out_size) {
    const float* p = (const float*)d_in[0];
    const float* q = (const float*)d_in[1];
    float* out = (float*)d_out;

    int cb = in_sizes[0] / (NPTS * 4);   // = 128 for (2,64,1024,4)
    if (cb > CB_MAX) cb = CB_MAX;

    chamfer_pair_kernel<<<cb, THREADS>>>(p, q, out, cb);
}